// round 14
// baseline (speedup 1.0000x reference)
#include <cuda_runtime.h>
#include <cuda_fp16.h>
#include <cuda_pipeline.h>
#include <mma.h>
using namespace nvcuda;

#define D 128
#define AHL 136   // half-array smem row stride (halves)
#define WBYTES (128 * AHL * 2)   // 34816
#define ABYTES (128 * AHL * 2)   // 34816
#define GEMM_BLKS 148
constexpr int MAXN = 100000;
constexpr int MAXE = 1600000;

// ---------------- scratch (device globals: allocation-free) ----------------
__device__ int   g_deg[MAXN];
__device__ int   g_fill[MAXN];
__device__ float g_dinv[MAXN];
__device__ int   g_rowptr[MAXN + 1];
__device__ int   g_bsum[128];
__device__ int   g_boff[128];
__device__ __align__(16) int2   g_edge[MAXE];                // (src, weight-bits)
__device__ __align__(16) __half g_W16[4 * D * D];            // fp16 weights
__device__ __align__(16) __half g_msg16[(size_t)MAXN * D];   // GEMM output (messages)
__device__ __align__(16) __half g_h16[(size_t)MAXN * D];     // activations / GEMM input

// ---------------- preprocessing ----------------
// zero deg/fill + convert W to fp16
__global__ void k_init(const float* __restrict__ Ws, int N) {
    int i = blockIdx.x * blockDim.x + threadIdx.x;
    if (i < N) { g_deg[i] = 0; g_fill[i] = 0; }
    if (i < 4 * D * D / 4) {
        float4 v = ((const float4*)Ws)[i];
        __half2 p0 = __floats2half2_rn(v.x, v.y);
        __half2 p1 = __floats2half2_rn(v.z, v.w);
        uint2 u;
        u.x = *(unsigned int*)&p0;
        u.y = *(unsigned int*)&p1;
        ((uint2*)g_W16)[i] = u;
    }
}

// scan phase 1 + fused dinv
__global__ void k_scan1(int N) {
    __shared__ int s[1024];
    int tid = threadIdx.x;
    int i = blockIdx.x * 1024 + tid;
    int v = (i < N) ? g_deg[i] : 0;
    if (i < N) g_dinv[i] = rsqrtf((float)(v + 1));   // +1 self-loop
    s[tid] = v;
    __syncthreads();
#pragma unroll
    for (int off = 1; off < 1024; off <<= 1) {
        int t = (tid >= off) ? s[tid - off] : 0;
        __syncthreads();
        s[tid] += t;
        __syncthreads();
    }
    if (i < N) g_rowptr[i] = s[tid] - v;
    if (tid == 1023) g_bsum[blockIdx.x] = s[1023];
}

__global__ void k_scan2(int nb, int N) {
    __shared__ int s[1024];
    int tid = threadIdx.x;
    int v = (tid < nb) ? g_bsum[tid] : 0;
    s[tid] = v;
    __syncthreads();
#pragma unroll
    for (int off = 1; off < 1024; off <<= 1) {
        int t = (tid >= off) ? s[tid - off] : 0;
        __syncthreads();
        s[tid] += t;
        __syncthreads();
    }
    if (tid < nb) g_boff[tid] = s[tid] - v;
    if (tid == nb - 1) g_rowptr[N] = s[tid];
}

__global__ void k_scan3(int N) {
    int i = blockIdx.x * 1024 + threadIdx.x;
    if (i < N) g_rowptr[i] += g_boff[blockIdx.x];
}

__global__ void k_fill(const int* __restrict__ ei, int E) {
    int e = blockIdx.x * blockDim.x + threadIdx.x;
    if (e < E) {
        int r = ei[e];
        int c = ei[E + e];
        int p = g_rowptr[c] + atomicAdd(&g_fill[c], 1);
        g_edge[p] = make_int2(r, __float_as_int(g_dinv[r] * g_dinv[c]));
    }
}

// ---------------- shared GEMM pieces ----------------
__device__ __forceinline__ void gemm_mma_epilogue(
    __half* Wh, __half* bA, int t, int N, int tid) {
    int warp = tid >> 5;
    int lane = tid & 31;
    int wy = warp >> 1;
    int wx = warp & 1;
    int rloc = wy * 32;
    int c0   = wx * 64;

    wmma::fragment<wmma::accumulator, 16, 16, 16, float> acc[2][4];
#pragma unroll
    for (int i = 0; i < 2; i++)
#pragma unroll
        for (int j = 0; j < 4; j++) wmma::fill_fragment(acc[i][j], 0.f);

#pragma unroll
    for (int k = 0; k < 128; k += 16) {
        wmma::fragment<wmma::matrix_a, 16, 16, 16, __half, wmma::row_major> a0, a1;
        wmma::load_matrix_sync(a0, bA + rloc * AHL + k, AHL);
        wmma::load_matrix_sync(a1, bA + (rloc + 16) * AHL + k, AHL);
#pragma unroll
        for (int j = 0; j < 4; j++) {
            wmma::fragment<wmma::matrix_b, 16, 16, 16, __half, wmma::row_major> b;
            wmma::load_matrix_sync(b, Wh + k * AHL + c0 + j * 16, AHL);
            wmma::mma_sync(acc[0][j], a0, b, acc[0][j]);
            wmma::mma_sync(acc[1][j], a1, b, acc[1][j]);
        }
    }
    __syncthreads();   // all warps done reading bA -> reuse as epilogue slab

    float* slab = (float*)bA + warp * (16 * 68);
    int row0 = t * 128;
#pragma unroll
    for (int p = 0; p < 2; p++) {
#pragma unroll
        for (int j = 0; j < 4; j++)
            wmma::store_matrix_sync(slab + j * 16, acc[p][j], 68, wmma::mem_row_major);
        __syncwarp();
#pragma unroll
        for (int i = 0; i < 8; i++) {
            int idx = i * 32 + lane;      // 0..255
            int r   = idx >> 4;           // 0..15
            int c4  = idx & 15;
            int grow = row0 + rloc + p * 16 + r;
            if (grow < N) {
                float4 v = *(const float4*)&slab[r * 68 + c4 * 4];
                __half2 p0 = __floats2half2_rn(v.x, v.y);
                __half2 p1 = __floats2half2_rn(v.z, v.w);
                uint2 u;
                u.x = *(unsigned int*)&p0;
                u.y = *(unsigned int*)&p1;
                ((uint2*)(g_msg16 + (size_t)grow * D + c0))[c4] = u;
            }
        }
        __syncwarp();
    }
}

// ---------------- fat kernel: layer-0 GEMM (blocks 0..147) || histogram (148..295) ----------------
__global__ __launch_bounds__(256) void k_g0h(const float* __restrict__ x,
                                             const int* __restrict__ ei,
                                             int N, int E, int ntiles) {
    extern __shared__ char smbase[];
    int tid = threadIdx.x;
    int bid = blockIdx.x;

    if (bid >= GEMM_BLKS) {
        // histogram: grid-stride over destination indices
        int stride = (gridDim.x - GEMM_BLKS) * blockDim.x;
        for (int e = (bid - GEMM_BLKS) * blockDim.x + tid; e < E; e += stride)
            atomicAdd(&g_deg[ei[E + e]], 1);
        return;
    }

    // layer-0 GEMM: persistent, W resident, A loaded fp32->fp16 inline
    __half* Wh  = (__half*)smbase;               // [128][AHL]
    __half* buf = (__half*)(smbase + WBYTES);    // [128][AHL]

#pragma unroll
    for (int i = 0; i < 8; i++) {
        int idx = i * 256 + tid;
        int r = idx >> 4, c8 = idx & 15;
        uint4 wu = ((const uint4*)(g_W16 + (size_t)r * D))[c8];
        *(uint4*)&Wh[r * AHL + c8 * 8] = wu;
    }
    __syncthreads();

    for (int t = bid; t < ntiles; t += GEMM_BLKS) {
        // load A tile from fp32 x, convert
#pragma unroll
        for (int i = 0; i < 8; i++) {
            int idx = i * 256 + tid;          // 0..2047
            int r   = idx >> 4;               // row 0..127
            int c8  = idx & 15;
            uint4 au = make_uint4(0u, 0u, 0u, 0u);
            int grow = t * 128 + r;
            if (grow < N) {
                const float4* xr = (const float4*)(x + (size_t)grow * D + c8 * 8);
                float4 a0 = xr[0], a1 = xr[1];
                __half2 p0 = __floats2half2_rn(a0.x, a0.y);
                __half2 p1 = __floats2half2_rn(a0.z, a0.w);
                __half2 p2 = __floats2half2_rn(a1.x, a1.y);
                __half2 p3 = __floats2half2_rn(a1.z, a1.w);
                au.x = *(unsigned int*)&p0;
                au.y = *(unsigned int*)&p1;
                au.z = *(unsigned int*)&p2;
                au.w = *(unsigned int*)&p3;
            }
            *(uint4*)&buf[r * AHL + c8 * 8] = au;
        }
        __syncthreads();
        gemm_mma_epilogue(Wh, buf, t, N, tid);
        __syncthreads();
    }
}

// ---------------- GEMM layers 1-3: persistent, W resident, cp.async double-buffered A ----------------
__device__ __forceinline__ void load_tile_async(__half* buf, int t, int N, int tid) {
#pragma unroll
    for (int i = 0; i < 4; i++) {
        int idx  = i * 256 + tid;
        int idx2 = idx + 1024;
        int r  = idx >> 4,  c8  = idx & 15;
        int r2 = idx2 >> 4, c82 = idx2 & 15;
        int grow  = t * 128 + r;
        int grow2 = t * 128 + r2;
        if (grow < N)
            __pipeline_memcpy_async(&buf[r * AHL + c8 * 8],
                                    g_h16 + (size_t)grow * D + c8 * 8, 16);
        if (grow2 < N)
            __pipeline_memcpy_async(&buf[r2 * AHL + c82 * 8],
                                    g_h16 + (size_t)grow2 * D + c82 * 8, 16);
    }
}

__global__ __launch_bounds__(256) void k_gemm_h(int loff, int N, int ntiles) {
    extern __shared__ char smbase[];
    __half* Wh   = (__half*)smbase;                        // [128][AHL]
    __half* buf0 = (__half*)(smbase + WBYTES);
    __half* buf1 = (__half*)(smbase + WBYTES + ABYTES);
    const __half* Wh16 = g_W16 + loff;
    int tid = threadIdx.x;

#pragma unroll
    for (int i = 0; i < 8; i++) {
        int idx = i * 256 + tid;
        int r = idx >> 4, c8 = idx & 15;
        uint4 wu = ((const uint4*)(Wh16 + (size_t)r * D))[c8];
        *(uint4*)&Wh[r * AHL + c8 * 8] = wu;
    }

    int t0 = blockIdx.x;
    if (t0 < ntiles) {
        load_tile_async(buf0, t0, N, tid);
        __pipeline_commit();
        __pipeline_wait_prior(0);
    }
    __syncthreads();

    int cur = 0;
    for (int t = t0; t < ntiles; t += gridDim.x) {
        __half* bA = cur ? buf1 : buf0;
        __half* bN = cur ? buf0 : buf1;
        int tn = t + gridDim.x;
        if (tn < ntiles) {
            load_tile_async(bN, tn, N, tid);
            __pipeline_commit();
        }
        gemm_mma_epilogue(Wh, bA, t, N, tid);
        if (tn < ntiles) __pipeline_wait_prior(0);
        __syncthreads();
        cur ^= 1;
    }
}

// ---------------- aggregation (gather, CSR by dest, shfl-distributed edges) ----------------
__device__ __forceinline__ void fma_row(const uint2& m, float w,
                                        float& ax, float& ay, float& az, float& aw) {
    float2 m0 = __half22float2(*(__half2*)&m.x);
    float2 m1 = __half22float2(*(__half2*)&m.y);
    ax = fmaf(m0.x, w, ax);
    ay = fmaf(m0.y, w, ay);
    az = fmaf(m1.x, w, az);
    aw = fmaf(m1.y, w, aw);
}

__global__ void __launch_bounds__(256) k_agg(const float* __restrict__ bias, int N) {
    int gt   = blockIdx.x * blockDim.x + threadIdx.x;
    int v    = gt >> 5;
    int lane = gt & 31;
    if (v >= N) return;

    float s  = g_dinv[v];
    float w0 = s * s;

    uint2 u = ((const uint2*)(g_msg16 + (size_t)v * D))[lane];
    float2 f0 = __half22float2(*(__half2*)&u.x);
    float2 f1 = __half22float2(*(__half2*)&u.y);
    float ax = f0.x * w0, ay = f0.y * w0, az = f1.x * w0, aw = f1.y * w0;

    int j   = g_rowptr[v];
    int end = g_rowptr[v + 1];

    while (j < end) {
        int avail = end - j;
        int cnt = avail < 32 ? avail : 32;
        int2 el = make_int2(0, 0);
        if (lane < cnt) el = __ldg(&g_edge[j + lane]);
        j += cnt;

        int t = 0;
        for (; t + 8 <= cnt; t += 8) {
            int  s0 = __shfl_sync(0xffffffffu, el.x, t);
            int  s1 = __shfl_sync(0xffffffffu, el.x, t + 1);
            int  s2 = __shfl_sync(0xffffffffu, el.x, t + 2);
            int  s3 = __shfl_sync(0xffffffffu, el.x, t + 3);
            int  s4 = __shfl_sync(0xffffffffu, el.x, t + 4);
            int  s5 = __shfl_sync(0xffffffffu, el.x, t + 5);
            int  s6 = __shfl_sync(0xffffffffu, el.x, t + 6);
            int  s7 = __shfl_sync(0xffffffffu, el.x, t + 7);
            float q0 = __int_as_float(__shfl_sync(0xffffffffu, el.y, t));
            float q1 = __int_as_float(__shfl_sync(0xffffffffu, el.y, t + 1));
            float q2 = __int_as_float(__shfl_sync(0xffffffffu, el.y, t + 2));
            float q3 = __int_as_float(__shfl_sync(0xffffffffu, el.y, t + 3));
            float q4 = __int_as_float(__shfl_sync(0xffffffffu, el.y, t + 4));
            float q5 = __int_as_float(__shfl_sync(0xffffffffu, el.y, t + 5));
            float q6 = __int_as_float(__shfl_sync(0xffffffffu, el.y, t + 6));
            float q7 = __int_as_float(__shfl_sync(0xffffffffu, el.y, t + 7));
            uint2 m0 = ((const uint2*)(g_msg16 + (size_t)s0 * D))[lane];
            uint2 m1 = ((const uint2*)(g_msg16 + (size_t)s1 * D))[lane];
            uint2 m2 = ((const uint2*)(g_msg16 + (size_t)s2 * D))[lane];
            uint2 m3 = ((const uint2*)(g_msg16 + (size_t)s3 * D))[lane];
            uint2 m4 = ((const uint2*)(g_msg16 + (size_t)s4 * D))[lane];
            uint2 m5 = ((const uint2*)(g_msg16 + (size_t)s5 * D))[lane];
            uint2 m6 = ((const uint2*)(g_msg16 + (size_t)s6 * D))[lane];
            uint2 m7 = ((const uint2*)(g_msg16 + (size_t)s7 * D))[lane];
            fma_row(m0, q0, ax, ay, az, aw);
            fma_row(m1, q1, ax, ay, az, aw);
            fma_row(m2, q2, ax, ay, az, aw);
            fma_row(m3, q3, ax, ay, az, aw);
            fma_row(m4, q4, ax, ay, az, aw);
            fma_row(m5, q5, ax, ay, az, aw);
            fma_row(m6, q6, ax, ay, az, aw);
            fma_row(m7, q7, ax, ay, az, aw);
        }
        for (; t + 4 <= cnt; t += 4) {
            int  s0 = __shfl_sync(0xffffffffu, el.x, t);
            int  s1 = __shfl_sync(0xffffffffu, el.x, t + 1);
            int  s2 = __shfl_sync(0xffffffffu, el.x, t + 2);
            int  s3 = __shfl_sync(0xffffffffu, el.x, t + 3);
            float q0 = __int_as_float(__shfl_sync(0xffffffffu, el.y, t));
            float q1 = __int_as_float(__shfl_sync(0xffffffffu, el.y, t + 1));
            float q2 = __int_as_float(__shfl_sync(0xffffffffu, el.y, t + 2));
            float q3 = __int_as_float(__shfl_sync(0xffffffffu, el.y, t + 3));
            uint2 m0 = ((const uint2*)(g_msg16 + (size_t)s0 * D))[lane];
            uint2 m1 = ((const uint2*)(g_msg16 + (size_t)s1 * D))[lane];
            uint2 m2 = ((const uint2*)(g_msg16 + (size_t)s2 * D))[lane];
            uint2 m3 = ((const uint2*)(g_msg16 + (size_t)s3 * D))[lane];
            fma_row(m0, q0, ax, ay, az, aw);
            fma_row(m1, q1, ax, ay, az, aw);
            fma_row(m2, q2, ax, ay, az, aw);
            fma_row(m3, q3, ax, ay, az, aw);
        }
        for (; t < cnt; t++) {
            int  s0 = __shfl_sync(0xffffffffu, el.x, t);
            float q0 = __int_as_float(__shfl_sync(0xffffffffu, el.y, t));
            uint2 m0 = ((const uint2*)(g_msg16 + (size_t)s0 * D))[lane];
            fma_row(m0, q0, ax, ay, az, aw);
        }
    }

    float4 b = ((const float4*)bias)[lane];
    ax = fmaxf(ax + b.x, 0.f);
    ay = fmaxf(ay + b.y, 0.f);
    az = fmaxf(az + b.z, 0.f);
    aw = fmaxf(aw + b.w, 0.f);
    __half2 p0 = __floats2half2_rn(ax, ay);
    __half2 p1 = __floats2half2_rn(az, aw);
    uint2 o;
    o.x = *(unsigned int*)&p0;
    o.y = *(unsigned int*)&p1;
    ((uint2*)(g_h16 + (size_t)v * D))[lane] = o;
}

// ---------------- pool + linear ----------------
__device__ __forceinline__ int lb(const int* a, int n, int key) {
    int lo = 0, hi = n;
    while (lo < hi) {
        int m = (lo + hi) >> 1;
        if (a[m] < key) lo = m + 1; else hi = m;
    }
    return lo;
}

__global__ void k_pool(const int* __restrict__ batch,
                       const float* __restrict__ Wl,
                       const float* __restrict__ bl,
                       float* __restrict__ out, int N) {
    int g = blockIdx.x;
    __shared__ int bounds[2];
    if (threadIdx.x == 0) bounds[0] = lb(batch, N, g);
    if (threadIdx.x == 1) bounds[1] = lb(batch, N, g + 1);
    __syncthreads();
    int lo = bounds[0], hi = bounds[1];
    int t = threadIdx.x;
    float sum = 0.f;
    for (int v = lo; v < hi; v++) sum += __half2float(g_h16[(size_t)v * D + t]);
    float cnt  = (float)(hi - lo);
    float mean = sum / fmaxf(cnt, 1.f);
    float p    = mean * Wl[t];
    __shared__ float red[128];
    red[t] = p;
    __syncthreads();
    for (int off = 64; off > 0; off >>= 1) {
        if (t < off) red[t] += red[t + off];
        __syncthreads();
    }
    if (t == 0) out[g] = red[0] + bl[0];
}

// ---------------- launch ----------------
extern "C" void kernel_launch(void* const* d_in, const int* in_sizes, int n_in,
                              void* d_out, int out_size) {
    const float* x     = nullptr;
    const int*   ei    = nullptr;
    const int*   batch = nullptr;
    const float* Ws    = nullptr;
    const float* bs    = nullptr;
    const float* Wl    = nullptr;
    const float* bl    = nullptr;
    int N = 0, E = 0;

    long long sx = 0;
    for (int i = 0; i < n_in; i++) if ((long long)in_sizes[i] > sx) sx = in_sizes[i];
    N = (int)(sx / D);
    for (int i = 0; i < n_in; i++) {
        long long s = in_sizes[i];
        if (s == sx)                x     = (const float*)d_in[i];
        else if (s == (long long)N) batch = (const int*)d_in[i];
        else if (s == 4LL * D * D)  Ws    = (const float*)d_in[i];
        else if (s == 4LL * D)      bs    = (const float*)d_in[i];
        else if (s == D)            Wl    = (const float*)d_in[i];
        else if (s == 1)            bl    = (const float*)d_in[i];
        else                        { ei = (const int*)d_in[i]; E = (int)(s / 2); }
    }
    float* out = (float*)d_out;

    const int smem_g0   = WBYTES + ABYTES;        // 69632
    const int smem_gemm = WBYTES + 2 * ABYTES;    // 104448
    cudaFuncSetAttribute(k_g0h,    cudaFuncAttributeMaxDynamicSharedMemorySize, smem_g0);
    cudaFuncSetAttribute(k_gemm_h, cudaFuncAttributeMaxDynamicSharedMemorySize, smem_gemm);

    int nb = (N + 1023) / 1024;
    int ntiles = (N + 127) / 128;
    int initmax = (N > 4 * D * D / 4) ? N : 4 * D * D / 4;

    k_init<<<(initmax + 255) / 256, 256>>>(Ws, N);
    // fat kernel: layer-0 GEMM (148 blocks) || degree histogram (148 blocks)
    k_g0h<<<2 * GEMM_BLKS, 256, smem_g0>>>(x, ei, N, E, ntiles);
    k_scan1<<<nb, 1024>>>(N);
    k_scan2<<<1, 1024>>>(nb, N);
    k_scan3<<<nb, 1024>>>(N);
    k_fill<<<(E + 255) / 256, 256>>>(ei, E);

    int aggblocks = (N * 32 + 255) / 256;
    k_agg<<<aggblocks, 256>>>(bs, N);   // layer 0 aggregate

    int gemm_grid = GEMM_BLKS;
    if (gemm_grid > ntiles) gemm_grid = ntiles;
    for (int l = 1; l < 4; l++) {
        k_gemm_h<<<gemm_grid, 256, smem_gemm>>>(l * D * D, N, ntiles);
        k_agg<<<aggblocks, 256>>>(bs + (size_t)l * D, N);
    }

    k_pool<<<out_size, 128>>>(batch, Wl, bl, out, N);
}

// round 15
// speedup vs baseline: 1.0205x; 1.0205x over previous
#include <cuda_runtime.h>
#include <cuda_fp16.h>
#include <mma.h>
using namespace nvcuda;

#define D 128
#define AHL 136   // half-array smem row stride (halves)
constexpr int MAXN = 100000;
constexpr int MAXE = 1600000;

// ---------------- scratch (device globals: allocation-free) ----------------
__device__ int   g_deg[MAXN];
__device__ int   g_fill[MAXN];
__device__ float g_dinv[MAXN];
__device__ int   g_rowptr[MAXN + 1];   // block-local exclusive prefix; +boff at use
__device__ int   g_bsum[128];
__device__ int   g_boff[128];
__device__ __align__(16) int2   g_edge[MAXE];                // (src, weight-bits)
__device__ __align__(16) __half g_W16[4 * D * D];            // fp16 weights
__device__ __align__(16) __half g_msg16[(size_t)MAXN * D];   // GEMM output (messages)
__device__ __align__(16) __half g_h16[(size_t)MAXN * D];     // activations / GEMM input

// ---------------- preprocessing ----------------
// merged: zero deg/fill + convert W to fp16
__global__ void k_init(const float* __restrict__ Ws, int N) {
    int i = blockIdx.x * blockDim.x + threadIdx.x;
    if (i < N) { g_deg[i] = 0; g_fill[i] = 0; }
    if (i < 4 * D * D / 4) {
        float4 v = ((const float4*)Ws)[i];
        __half2 p0 = __floats2half2_rn(v.x, v.y);
        __half2 p1 = __floats2half2_rn(v.z, v.w);
        uint2 u;
        u.x = *(unsigned int*)&p0;
        u.y = *(unsigned int*)&p1;
        ((uint2*)g_W16)[i] = u;
    }
}

__global__ void k_hist(const int* __restrict__ ei, int E) {
    int e = blockIdx.x * blockDim.x + threadIdx.x;
    if (e < E) atomicAdd(&g_deg[ei[E + e]], 1);
}

// scan phase 1 (shfl-based, 2 syncs) + fused dinv. Produces block-local
// exclusive prefix in g_rowptr and per-block sums in g_bsum.
__global__ void k_scan1(int N) {
    __shared__ int wsum[32];
    int tid  = threadIdx.x;
    int lane = tid & 31;
    int warp = tid >> 5;
    int i = blockIdx.x * 1024 + tid;
    int v = (i < N) ? g_deg[i] : 0;
    if (i < N) g_dinv[i] = rsqrtf((float)(v + 1));   // +1 self-loop

    // warp inclusive scan
    int s = v;
#pragma unroll
    for (int off = 1; off < 32; off <<= 1) {
        int t = __shfl_up_sync(0xffffffffu, s, off);
        if (lane >= off) s += t;
    }
    if (lane == 31) wsum[warp] = s;
    __syncthreads();
    if (warp == 0) {
        int ws = wsum[lane];
#pragma unroll
        for (int off = 1; off < 32; off <<= 1) {
            int t = __shfl_up_sync(0xffffffffu, ws, off);
            if (lane >= off) ws += t;
        }
        wsum[lane] = ws;
    }
    __syncthreads();
    int prefix = (warp > 0) ? wsum[warp - 1] : 0;
    int incl = prefix + s;
    if (i < N) g_rowptr[i] = incl - v;        // exclusive, block-local
    if (tid == 1023) g_bsum[blockIdx.x] = incl;
}

// scan phase 2: exclusive scan of <=128 block sums (128 threads, shfl)
__global__ void k_scan2(int nb, int N) {
    __shared__ int wsum[4];
    int tid  = threadIdx.x;
    int lane = tid & 31;
    int warp = tid >> 5;
    int v = (tid < nb) ? g_bsum[tid] : 0;
    int s = v;
#pragma unroll
    for (int off = 1; off < 32; off <<= 1) {
        int t = __shfl_up_sync(0xffffffffu, s, off);
        if (lane >= off) s += t;
    }
    if (lane == 31) wsum[warp] = s;
    __syncthreads();
    if (tid == 0) {
        int a = 0;
#pragma unroll
        for (int w = 0; w < 4; w++) { int t = wsum[w]; wsum[w] = a; a += t; }
    }
    __syncthreads();
    int incl = wsum[warp] + s;
    if (tid < nb) g_boff[tid] = incl - v;     // exclusive over blocks
    if (tid == nb - 1) g_rowptr[N] = incl;    // grand total (absolute)
}

__global__ void k_fill(const int* __restrict__ ei, int E) {
    int e = blockIdx.x * blockDim.x + threadIdx.x;
    if (e < E) {
        int r = ei[e];
        int c = ei[E + e];
        int p = g_rowptr[c] + g_boff[c >> 10] + atomicAdd(&g_fill[c], 1);
        g_edge[p] = make_int2(r, __float_as_int(g_dinv[r] * g_dinv[c]));
    }
}

// ---------------- GEMM (fp16 WMMA m16n16k16, fp16 W from g_W16, warp-private epilogue) ----------------
__global__ __launch_bounds__(256) void k_gemm_h(int loff,
                                                const float* __restrict__ x,
                                                int N, int use_x) {
    extern __shared__ char smbase[];
    __half* Ah = (__half*)smbase;                       // [128][AHL]
    __half* Wh = (__half*)(smbase + 128 * AHL * 2);     // [128][AHL]
    const __half* Wh16 = g_W16 + loff;

    int tid  = threadIdx.x;
    int row0 = blockIdx.x * 128;

#pragma unroll
    for (int i = 0; i < 8; i++) {
        int idx = i * 256 + tid;          // 0..2047
        int r   = idx >> 4;               // row 0..127
        int c8  = idx & 15;               // uint4 group (8 halves)
        uint4 wu = ((const uint4*)(Wh16 + (size_t)r * D))[c8];
        *(uint4*)&Wh[r * AHL + c8 * 8] = wu;
        uint4 au = make_uint4(0u, 0u, 0u, 0u);
        int grow = row0 + r;
        if (grow < N) {
            if (use_x) {
                const float4* xr = (const float4*)(x + (size_t)grow * D + c8 * 8);
                float4 a0 = xr[0], a1 = xr[1];
                __half2 p0 = __floats2half2_rn(a0.x, a0.y);
                __half2 p1 = __floats2half2_rn(a0.z, a0.w);
                __half2 p2 = __floats2half2_rn(a1.x, a1.y);
                __half2 p3 = __floats2half2_rn(a1.z, a1.w);
                au.x = *(unsigned int*)&p0;
                au.y = *(unsigned int*)&p1;
                au.z = *(unsigned int*)&p2;
                au.w = *(unsigned int*)&p3;
            } else {
                au = ((const uint4*)(g_h16 + (size_t)grow * D))[c8];
            }
        }
        *(uint4*)&Ah[r * AHL + c8 * 8] = au;
    }
    __syncthreads();

    int warp = tid >> 5;
    int lane = tid & 31;
    int wy = warp >> 1;
    int wx = warp & 1;
    int rloc = wy * 32;
    int c0   = wx * 64;

    wmma::fragment<wmma::accumulator, 16, 16, 16, float> acc[2][4];
#pragma unroll
    for (int i = 0; i < 2; i++)
#pragma unroll
        for (int j = 0; j < 4; j++) wmma::fill_fragment(acc[i][j], 0.f);

#pragma unroll
    for (int k = 0; k < 128; k += 16) {
        wmma::fragment<wmma::matrix_a, 16, 16, 16, __half, wmma::row_major> a0, a1;
        wmma::load_matrix_sync(a0, Ah + rloc * AHL + k, AHL);
        wmma::load_matrix_sync(a1, Ah + (rloc + 16) * AHL + k, AHL);
#pragma unroll
        for (int j = 0; j < 4; j++) {
            wmma::fragment<wmma::matrix_b, 16, 16, 16, __half, wmma::row_major> b;
            wmma::load_matrix_sync(b, Wh + k * AHL + c0 + j * 16, AHL);
            wmma::mma_sync(acc[0][j], a0, b, acc[0][j]);
            wmma::mma_sync(acc[1][j], a1, b, acc[1][j]);
        }
    }

    // epilogue: one sync, then warp-private fp32 slab -> coalesced fp16 stores
    __syncthreads();
    float* slab = (float*)smbase + warp * (32 * 68);
#pragma unroll
    for (int j = 0; j < 4; j++) {
        wmma::store_matrix_sync(slab + j * 16,           acc[0][j], 68, wmma::mem_row_major);
        wmma::store_matrix_sync(slab + 16 * 68 + j * 16, acc[1][j], 68, wmma::mem_row_major);
    }
    __syncwarp();
#pragma unroll
    for (int i = 0; i < 16; i++) {
        int idx = i * 32 + lane;          // 0..511
        int r   = idx >> 4;               // 0..31
        int c4  = idx & 15;               // float4 group within 64 cols
        int grow = row0 + rloc + r;
        if (grow < N) {
            float4 v = *(const float4*)&slab[r * 68 + c4 * 4];
            __half2 p0 = __floats2half2_rn(v.x, v.y);
            __half2 p1 = __floats2half2_rn(v.z, v.w);
            uint2 u;
            u.x = *(unsigned int*)&p0;
            u.y = *(unsigned int*)&p1;
            ((uint2*)(g_msg16 + (size_t)grow * D + c0))[c4] = u;
        }
    }
}

// ---------------- aggregation (gather, CSR by dest, shfl-distributed edges) ----------------
__device__ __forceinline__ void fma_row(const uint2& m, float w,
                                        float& ax, float& ay, float& az, float& aw) {
    float2 m0 = __half22float2(*(__half2*)&m.x);
    float2 m1 = __half22float2(*(__half2*)&m.y);
    ax = fmaf(m0.x, w, ax);
    ay = fmaf(m0.y, w, ay);
    az = fmaf(m1.x, w, az);
    aw = fmaf(m1.y, w, aw);
}

__global__ void __launch_bounds__(256) k_agg(const float* __restrict__ bias, int N) {
    int gt   = blockIdx.x * blockDim.x + threadIdx.x;
    int v    = gt >> 5;
    int lane = gt & 31;
    if (v >= N) return;

    float s  = g_dinv[v];
    float w0 = s * s;

    uint2 u = ((const uint2*)(g_msg16 + (size_t)v * D))[lane];
    float2 f0 = __half22float2(*(__half2*)&u.x);
    float2 f1 = __half22float2(*(__half2*)&u.y);
    float ax = f0.x * w0, ay = f0.y * w0, az = f1.x * w0, aw = f1.y * w0;

    // fold block offsets into block-local rowptr
    int j   = g_rowptr[v] + g_boff[v >> 10];
    int vn  = v + 1;
    int end = g_rowptr[vn] + ((vn < N) ? g_boff[vn >> 10] : 0);

    while (j < end) {
        int avail = end - j;
        int cnt = avail < 32 ? avail : 32;
        int2 el = make_int2(0, 0);
        if (lane < cnt) el = __ldg(&g_edge[j + lane]);
        j += cnt;

        int t = 0;
        for (; t + 8 <= cnt; t += 8) {
            int  s0 = __shfl_sync(0xffffffffu, el.x, t);
            int  s1 = __shfl_sync(0xffffffffu, el.x, t + 1);
            int  s2 = __shfl_sync(0xffffffffu, el.x, t + 2);
            int  s3 = __shfl_sync(0xffffffffu, el.x, t + 3);
            int  s4 = __shfl_sync(0xffffffffu, el.x, t + 4);
            int  s5 = __shfl_sync(0xffffffffu, el.x, t + 5);
            int  s6 = __shfl_sync(0xffffffffu, el.x, t + 6);
            int  s7 = __shfl_sync(0xffffffffu, el.x, t + 7);
            float q0 = __int_as_float(__shfl_sync(0xffffffffu, el.y, t));
            float q1 = __int_as_float(__shfl_sync(0xffffffffu, el.y, t + 1));
            float q2 = __int_as_float(__shfl_sync(0xffffffffu, el.y, t + 2));
            float q3 = __int_as_float(__shfl_sync(0xffffffffu, el.y, t + 3));
            float q4 = __int_as_float(__shfl_sync(0xffffffffu, el.y, t + 4));
            float q5 = __int_as_float(__shfl_sync(0xffffffffu, el.y, t + 5));
            float q6 = __int_as_float(__shfl_sync(0xffffffffu, el.y, t + 6));
            float q7 = __int_as_float(__shfl_sync(0xffffffffu, el.y, t + 7));
            uint2 m0 = ((const uint2*)(g_msg16 + (size_t)s0 * D))[lane];
            uint2 m1 = ((const uint2*)(g_msg16 + (size_t)s1 * D))[lane];
            uint2 m2 = ((const uint2*)(g_msg16 + (size_t)s2 * D))[lane];
            uint2 m3 = ((const uint2*)(g_msg16 + (size_t)s3 * D))[lane];
            uint2 m4 = ((const uint2*)(g_msg16 + (size_t)s4 * D))[lane];
            uint2 m5 = ((const uint2*)(g_msg16 + (size_t)s5 * D))[lane];
            uint2 m6 = ((const uint2*)(g_msg16 + (size_t)s6 * D))[lane];
            uint2 m7 = ((const uint2*)(g_msg16 + (size_t)s7 * D))[lane];
            fma_row(m0, q0, ax, ay, az, aw);
            fma_row(m1, q1, ax, ay, az, aw);
            fma_row(m2, q2, ax, ay, az, aw);
            fma_row(m3, q3, ax, ay, az, aw);
            fma_row(m4, q4, ax, ay, az, aw);
            fma_row(m5, q5, ax, ay, az, aw);
            fma_row(m6, q6, ax, ay, az, aw);
            fma_row(m7, q7, ax, ay, az, aw);
        }
        for (; t + 4 <= cnt; t += 4) {
            int  s0 = __shfl_sync(0xffffffffu, el.x, t);
            int  s1 = __shfl_sync(0xffffffffu, el.x, t + 1);
            int  s2 = __shfl_sync(0xffffffffu, el.x, t + 2);
            int  s3 = __shfl_sync(0xffffffffu, el.x, t + 3);
            float q0 = __int_as_float(__shfl_sync(0xffffffffu, el.y, t));
            float q1 = __int_as_float(__shfl_sync(0xffffffffu, el.y, t + 1));
            float q2 = __int_as_float(__shfl_sync(0xffffffffu, el.y, t + 2));
            float q3 = __int_as_float(__shfl_sync(0xffffffffu, el.y, t + 3));
            uint2 m0 = ((const uint2*)(g_msg16 + (size_t)s0 * D))[lane];
            uint2 m1 = ((const uint2*)(g_msg16 + (size_t)s1 * D))[lane];
            uint2 m2 = ((const uint2*)(g_msg16 + (size_t)s2 * D))[lane];
            uint2 m3 = ((const uint2*)(g_msg16 + (size_t)s3 * D))[lane];
            fma_row(m0, q0, ax, ay, az, aw);
            fma_row(m1, q1, ax, ay, az, aw);
            fma_row(m2, q2, ax, ay, az, aw);
            fma_row(m3, q3, ax, ay, az, aw);
        }
        for (; t < cnt; t++) {
            int  s0 = __shfl_sync(0xffffffffu, el.x, t);
            float q0 = __int_as_float(__shfl_sync(0xffffffffu, el.y, t));
            uint2 m0 = ((const uint2*)(g_msg16 + (size_t)s0 * D))[lane];
            fma_row(m0, q0, ax, ay, az, aw);
        }
    }

    float4 b = ((const float4*)bias)[lane];
    ax = fmaxf(ax + b.x, 0.f);
    ay = fmaxf(ay + b.y, 0.f);
    az = fmaxf(az + b.z, 0.f);
    aw = fmaxf(aw + b.w, 0.f);
    __half2 p0 = __floats2half2_rn(ax, ay);
    __half2 p1 = __floats2half2_rn(az, aw);
    uint2 o;
    o.x = *(unsigned int*)&p0;
    o.y = *(unsigned int*)&p1;
    ((uint2*)(g_h16 + (size_t)v * D))[lane] = o;
}

// ---------------- pool + linear ----------------
__device__ __forceinline__ int lb(const int* a, int n, int key) {
    int lo = 0, hi = n;
    while (lo < hi) {
        int m = (lo + hi) >> 1;
        if (a[m] < key) lo = m + 1; else hi = m;
    }
    return lo;
}

__global__ void k_pool(const int* __restrict__ batch,
                       const float* __restrict__ Wl,
                       const float* __restrict__ bl,
                       float* __restrict__ out, int N) {
    int g = blockIdx.x;
    __shared__ int bounds[2];
    if (threadIdx.x == 0) bounds[0] = lb(batch, N, g);
    if (threadIdx.x == 1) bounds[1] = lb(batch, N, g + 1);
    __syncthreads();
    int lo = bounds[0], hi = bounds[1];
    int t = threadIdx.x;
    float sum = 0.f;
    for (int v = lo; v < hi; v++) sum += __half2float(g_h16[(size_t)v * D + t]);
    float cnt  = (float)(hi - lo);
    float mean = sum / fmaxf(cnt, 1.f);
    float p    = mean * Wl[t];
    __shared__ float red[128];
    red[t] = p;
    __syncthreads();
    for (int off = 64; off > 0; off >>= 1) {
        if (t < off) red[t] += red[t + off];
        __syncthreads();
    }
    if (t == 0) out[g] = red[0] + bl[0];
}

// ---------------- launch ----------------
extern "C" void kernel_launch(void* const* d_in, const int* in_sizes, int n_in,
                              void* d_out, int out_size) {
    const float* x     = nullptr;
    const int*   ei    = nullptr;
    const int*   batch = nullptr;
    const float* Ws    = nullptr;
    const float* bs    = nullptr;
    const float* Wl    = nullptr;
    const float* bl    = nullptr;
    int N = 0, E = 0;

    long long sx = 0;
    for (int i = 0; i < n_in; i++) if ((long long)in_sizes[i] > sx) sx = in_sizes[i];
    N = (int)(sx / D);
    for (int i = 0; i < n_in; i++) {
        long long s = in_sizes[i];
        if (s == sx)                x     = (const float*)d_in[i];
        else if (s == (long long)N) batch = (const int*)d_in[i];
        else if (s == 4LL * D * D)  Ws    = (const float*)d_in[i];
        else if (s == 4LL * D)      bs    = (const float*)d_in[i];
        else if (s == D)            Wl    = (const float*)d_in[i];
        else if (s == 1)            bl    = (const float*)d_in[i];
        else                        { ei = (const int*)d_in[i]; E = (int)(s / 2); }
    }
    float* out = (float*)d_out;

    const int smem_bytes = 2 * 128 * AHL * 2;   // 69632 bytes
    cudaFuncSetAttribute(k_gemm_h, cudaFuncAttributeMaxDynamicSharedMemorySize, smem_bytes);

    int nb = (N + 1023) / 1024;
    int initmax = (N > 4 * D * D / 4) ? N : 4 * D * D / 4;

    k_init<<<(initmax + 255) / 256, 256>>>(Ws, N);
    k_hist<<<(E + 255) / 256, 256>>>(ei, E);
    k_scan1<<<nb, 1024>>>(N);
    k_scan2<<<1, 128>>>(nb, N);
    k_fill<<<(E + 255) / 256, 256>>>(ei, E);

    int gblocks = (N + 127) / 128;
    int aggblocks = (N * 32 + 255) / 256;
    for (int l = 0; l < 4; l++) {
        k_gemm_h<<<gblocks, 256, smem_bytes>>>(l * D * D, x, N, l == 0 ? 1 : 0);
        k_agg<<<aggblocks, 256>>>(bs + (size_t)l * D, N);
    }

    k_pool<<<out_size, 128>>>(batch, Wl, bl, out, N);
}

// round 16
// speedup vs baseline: 1.0228x; 1.0022x over previous
#include <cuda_runtime.h>
#include <cuda_fp16.h>
#include <mma.h>
using namespace nvcuda;

#define D 128
#define AHL 136   // half-array smem row stride (halves)
constexpr int MAXN = 100000;
constexpr int MAXE = 1600000;

// ---------------- scratch (device globals: allocation-free) ----------------
__device__ int   g_deg[MAXN];
__device__ int   g_fill[MAXN];
__device__ float g_dinv[MAXN];
__device__ int   g_rowptr[MAXN + 1];   // block-local exclusive prefix; +boff at use
__device__ int   g_bsum[128];
__device__ int   g_boff[128];
__device__ int   g_ctr;                // last-block counter for fused scan
__device__ __align__(16) int2   g_edge[MAXE];                // (src, weight-bits)
__device__ __align__(16) __half g_W16[4 * D * D];            // fp16 weights
__device__ __align__(16) __half g_msg16[(size_t)MAXN * D];   // GEMM output (messages)
__device__ __align__(16) __half g_h16[(size_t)MAXN * D];     // activations / GEMM input

// ---------------- preprocessing ----------------
// merged: zero deg/fill/ctr + convert W to fp16
__global__ void k_init(const float* __restrict__ Ws, int N) {
    int i = blockIdx.x * blockDim.x + threadIdx.x;
    if (i == 0) g_ctr = 0;
    if (i < N) { g_deg[i] = 0; g_fill[i] = 0; }
    if (i < 4 * D * D / 4) {
        float4 v = ((const float4*)Ws)[i];
        __half2 p0 = __floats2half2_rn(v.x, v.y);
        __half2 p1 = __floats2half2_rn(v.z, v.w);
        uint2 u;
        u.x = *(unsigned int*)&p0;
        u.y = *(unsigned int*)&p1;
        ((uint2*)g_W16)[i] = u;
    }
}

// histogram over destination indices, int2-vectorized (2 edges/thread)
__global__ void k_hist(const int* __restrict__ ei, int E) {
    int i = blockIdx.x * blockDim.x + threadIdx.x;
    int e = i * 2;
    if (e + 1 < E) {
        int2 cc = *(const int2*)(ei + E + e);
        atomicAdd(&g_deg[cc.x], 1);
        atomicAdd(&g_deg[cc.y], 1);
    } else if (e < E) {
        atomicAdd(&g_deg[ei[E + e]], 1);
    }
}

// scan phase 1 (shfl, 2 syncs) + fused dinv + fused last-block scan of block sums.
__global__ void k_scan1(int N, int nb) {
    __shared__ int wsum[32];
    __shared__ int w2[4];
    __shared__ int is_last;
    int tid  = threadIdx.x;
    int lane = tid & 31;
    int warp = tid >> 5;
    int i = blockIdx.x * 1024 + tid;
    int v = (i < N) ? g_deg[i] : 0;
    if (i < N) g_dinv[i] = rsqrtf((float)(v + 1));   // +1 self-loop

    // warp inclusive scan
    int s = v;
#pragma unroll
    for (int off = 1; off < 32; off <<= 1) {
        int t = __shfl_up_sync(0xffffffffu, s, off);
        if (lane >= off) s += t;
    }
    if (lane == 31) wsum[warp] = s;
    __syncthreads();
    if (warp == 0) {
        int ws = wsum[lane];
#pragma unroll
        for (int off = 1; off < 32; off <<= 1) {
            int t = __shfl_up_sync(0xffffffffu, ws, off);
            if (lane >= off) ws += t;
        }
        wsum[lane] = ws;
    }
    __syncthreads();
    int prefix = (warp > 0) ? wsum[warp - 1] : 0;
    int incl = prefix + s;
    if (i < N) g_rowptr[i] = incl - v;        // exclusive, block-local

    if (tid == 1023) {
        g_bsum[blockIdx.x] = incl;
        __threadfence();
        int c = atomicAdd(&g_ctr, 1);
        is_last = (c == nb - 1) ? 1 : 0;
    }
    __syncthreads();
    if (!is_last) return;

    // last block: exclusive scan of nb (<=128) block sums -> g_boff
    int vv = 0, ss = 0;
    if (tid < 128) {
        vv = (tid < nb) ? g_bsum[tid] : 0;
        ss = vv;
#pragma unroll
        for (int off = 1; off < 32; off <<= 1) {
            int t = __shfl_up_sync(0xffffffffu, ss, off);
            if (lane >= off) ss += t;
        }
        if (lane == 31) w2[warp] = ss;
    }
    __syncthreads();
    if (tid == 0) {
        int a = 0;
#pragma unroll
        for (int w = 0; w < 4; w++) { int t = w2[w]; w2[w] = a; a += t; }
    }
    __syncthreads();
    if (tid < 128) {
        int incl2 = w2[warp] + ss;
        if (tid < nb) g_boff[tid] = incl2 - vv;   // exclusive over blocks
        if (tid == nb - 1) g_rowptr[N] = incl2;   // grand total (absolute)
    }
}

__global__ void k_fill(const int* __restrict__ ei, int E) {
    int e = blockIdx.x * blockDim.x + threadIdx.x;
    if (e < E) {
        int r = ei[e];
        int c = ei[E + e];
        int p = g_rowptr[c] + g_boff[c >> 10] + atomicAdd(&g_fill[c], 1);
        g_edge[p] = make_int2(r, __float_as_int(g_dinv[r] * g_dinv[c]));
    }
}

// ---------------- GEMM (fp16 WMMA m16n16k16, fp16 W from g_W16, warp-private epilogue) ----------------
__global__ __launch_bounds__(256) void k_gemm_h(int loff,
                                                const float* __restrict__ x,
                                                int N, int use_x) {
    extern __shared__ char smbase[];
    __half* Ah = (__half*)smbase;                       // [128][AHL]
    __half* Wh = (__half*)(smbase + 128 * AHL * 2);     // [128][AHL]
    const __half* Wh16 = g_W16 + loff;

    int tid  = threadIdx.x;
    int row0 = blockIdx.x * 128;

#pragma unroll
    for (int i = 0; i < 8; i++) {
        int idx = i * 256 + tid;          // 0..2047
        int r   = idx >> 4;               // row 0..127
        int c8  = idx & 15;               // uint4 group (8 halves)
        uint4 wu = ((const uint4*)(Wh16 + (size_t)r * D))[c8];
        *(uint4*)&Wh[r * AHL + c8 * 8] = wu;
        uint4 au = make_uint4(0u, 0u, 0u, 0u);
        int grow = row0 + r;
        if (grow < N) {
            if (use_x) {
                const float4* xr = (const float4*)(x + (size_t)grow * D + c8 * 8);
                float4 a0 = xr[0], a1 = xr[1];
                __half2 p0 = __floats2half2_rn(a0.x, a0.y);
                __half2 p1 = __floats2half2_rn(a0.z, a0.w);
                __half2 p2 = __floats2half2_rn(a1.x, a1.y);
                __half2 p3 = __floats2half2_rn(a1.z, a1.w);
                au.x = *(unsigned int*)&p0;
                au.y = *(unsigned int*)&p1;
                au.z = *(unsigned int*)&p2;
                au.w = *(unsigned int*)&p3;
            } else {
                au = ((const uint4*)(g_h16 + (size_t)grow * D))[c8];
            }
        }
        *(uint4*)&Ah[r * AHL + c8 * 8] = au;
    }
    __syncthreads();

    int warp = tid >> 5;
    int lane = tid & 31;
    int wy = warp >> 1;
    int wx = warp & 1;
    int rloc = wy * 32;
    int c0   = wx * 64;

    wmma::fragment<wmma::accumulator, 16, 16, 16, float> acc[2][4];
#pragma unroll
    for (int i = 0; i < 2; i++)
#pragma unroll
        for (int j = 0; j < 4; j++) wmma::fill_fragment(acc[i][j], 0.f);

#pragma unroll
    for (int k = 0; k < 128; k += 16) {
        wmma::fragment<wmma::matrix_a, 16, 16, 16, __half, wmma::row_major> a0, a1;
        wmma::load_matrix_sync(a0, Ah + rloc * AHL + k, AHL);
        wmma::load_matrix_sync(a1, Ah + (rloc + 16) * AHL + k, AHL);
#pragma unroll
        for (int j = 0; j < 4; j++) {
            wmma::fragment<wmma::matrix_b, 16, 16, 16, __half, wmma::row_major> b;
            wmma::load_matrix_sync(b, Wh + k * AHL + c0 + j * 16, AHL);
            wmma::mma_sync(acc[0][j], a0, b, acc[0][j]);
            wmma::mma_sync(acc[1][j], a1, b, acc[1][j]);
        }
    }

    // epilogue: one sync, then warp-private fp32 slab -> coalesced fp16 stores
    __syncthreads();
    float* slab = (float*)smbase + warp * (32 * 68);
#pragma unroll
    for (int j = 0; j < 4; j++) {
        wmma::store_matrix_sync(slab + j * 16,           acc[0][j], 68, wmma::mem_row_major);
        wmma::store_matrix_sync(slab + 16 * 68 + j * 16, acc[1][j], 68, wmma::mem_row_major);
    }
    __syncwarp();
#pragma unroll
    for (int i = 0; i < 16; i++) {
        int idx = i * 32 + lane;          // 0..511
        int r   = idx >> 4;               // 0..31
        int c4  = idx & 15;               // float4 group within 64 cols
        int grow = row0 + rloc + r;
        if (grow < N) {
            float4 v = *(const float4*)&slab[r * 68 + c4 * 4];
            __half2 p0 = __floats2half2_rn(v.x, v.y);
            __half2 p1 = __floats2half2_rn(v.z, v.w);
            uint2 u;
            u.x = *(unsigned int*)&p0;
            u.y = *(unsigned int*)&p1;
            ((uint2*)(g_msg16 + (size_t)grow * D + c0))[c4] = u;
        }
    }
}

// ---------------- aggregation (gather, CSR by dest, shfl-distributed edges) ----------------
__device__ __forceinline__ void fma_row(const uint2& m, float w,
                                        float& ax, float& ay, float& az, float& aw) {
    float2 m0 = __half22float2(*(__half2*)&m.x);
    float2 m1 = __half22float2(*(__half2*)&m.y);
    ax = fmaf(m0.x, w, ax);
    ay = fmaf(m0.y, w, ay);
    az = fmaf(m1.x, w, az);
    aw = fmaf(m1.y, w, aw);
}

__global__ void __launch_bounds__(256) k_agg(const float* __restrict__ bias, int N) {
    int gt   = blockIdx.x * blockDim.x + threadIdx.x;
    int v    = gt >> 5;
    int lane = gt & 31;
    if (v >= N) return;

    float s  = g_dinv[v];
    float w0 = s * s;

    uint2 u = ((const uint2*)(g_msg16 + (size_t)v * D))[lane];
    float2 f0 = __half22float2(*(__half2*)&u.x);
    float2 f1 = __half22float2(*(__half2*)&u.y);
    float ax = f0.x * w0, ay = f0.y * w0, az = f1.x * w0, aw = f1.y * w0;

    // fold block offsets into block-local rowptr
    int j   = g_rowptr[v] + g_boff[v >> 10];
    int vn  = v + 1;
    int end = g_rowptr[vn] + ((vn < N) ? g_boff[vn >> 10] : 0);

    while (j < end) {
        int avail = end - j;
        int cnt = avail < 32 ? avail : 32;
        int2 el = make_int2(0, 0);
        if (lane < cnt) el = __ldg(&g_edge[j + lane]);
        j += cnt;

        int t = 0;
        for (; t + 8 <= cnt; t += 8) {
            int  s0 = __shfl_sync(0xffffffffu, el.x, t);
            int  s1 = __shfl_sync(0xffffffffu, el.x, t + 1);
            int  s2 = __shfl_sync(0xffffffffu, el.x, t + 2);
            int  s3 = __shfl_sync(0xffffffffu, el.x, t + 3);
            int  s4 = __shfl_sync(0xffffffffu, el.x, t + 4);
            int  s5 = __shfl_sync(0xffffffffu, el.x, t + 5);
            int  s6 = __shfl_sync(0xffffffffu, el.x, t + 6);
            int  s7 = __shfl_sync(0xffffffffu, el.x, t + 7);
            float q0 = __int_as_float(__shfl_sync(0xffffffffu, el.y, t));
            float q1 = __int_as_float(__shfl_sync(0xffffffffu, el.y, t + 1));
            float q2 = __int_as_float(__shfl_sync(0xffffffffu, el.y, t + 2));
            float q3 = __int_as_float(__shfl_sync(0xffffffffu, el.y, t + 3));
            float q4 = __int_as_float(__shfl_sync(0xffffffffu, el.y, t + 4));
            float q5 = __int_as_float(__shfl_sync(0xffffffffu, el.y, t + 5));
            float q6 = __int_as_float(__shfl_sync(0xffffffffu, el.y, t + 6));
            float q7 = __int_as_float(__shfl_sync(0xffffffffu, el.y, t + 7));
            uint2 m0 = ((const uint2*)(g_msg16 + (size_t)s0 * D))[lane];
            uint2 m1 = ((const uint2*)(g_msg16 + (size_t)s1 * D))[lane];
            uint2 m2 = ((const uint2*)(g_msg16 + (size_t)s2 * D))[lane];
            uint2 m3 = ((const uint2*)(g_msg16 + (size_t)s3 * D))[lane];
            uint2 m4 = ((const uint2*)(g_msg16 + (size_t)s4 * D))[lane];
            uint2 m5 = ((const uint2*)(g_msg16 + (size_t)s5 * D))[lane];
            uint2 m6 = ((const uint2*)(g_msg16 + (size_t)s6 * D))[lane];
            uint2 m7 = ((const uint2*)(g_msg16 + (size_t)s7 * D))[lane];
            fma_row(m0, q0, ax, ay, az, aw);
            fma_row(m1, q1, ax, ay, az, aw);
            fma_row(m2, q2, ax, ay, az, aw);
            fma_row(m3, q3, ax, ay, az, aw);
            fma_row(m4, q4, ax, ay, az, aw);
            fma_row(m5, q5, ax, ay, az, aw);
            fma_row(m6, q6, ax, ay, az, aw);
            fma_row(m7, q7, ax, ay, az, aw);
        }
        for (; t + 4 <= cnt; t += 4) {
            int  s0 = __shfl_sync(0xffffffffu, el.x, t);
            int  s1 = __shfl_sync(0xffffffffu, el.x, t + 1);
            int  s2 = __shfl_sync(0xffffffffu, el.x, t + 2);
            int  s3 = __shfl_sync(0xffffffffu, el.x, t + 3);
            float q0 = __int_as_float(__shfl_sync(0xffffffffu, el.y, t));
            float q1 = __int_as_float(__shfl_sync(0xffffffffu, el.y, t + 1));
            float q2 = __int_as_float(__shfl_sync(0xffffffffu, el.y, t + 2));
            float q3 = __int_as_float(__shfl_sync(0xffffffffu, el.y, t + 3));
            uint2 m0 = ((const uint2*)(g_msg16 + (size_t)s0 * D))[lane];
            uint2 m1 = ((const uint2*)(g_msg16 + (size_t)s1 * D))[lane];
            uint2 m2 = ((const uint2*)(g_msg16 + (size_t)s2 * D))[lane];
            uint2 m3 = ((const uint2*)(g_msg16 + (size_t)s3 * D))[lane];
            fma_row(m0, q0, ax, ay, az, aw);
            fma_row(m1, q1, ax, ay, az, aw);
            fma_row(m2, q2, ax, ay, az, aw);
            fma_row(m3, q3, ax, ay, az, aw);
        }
        for (; t < cnt; t++) {
            int  s0 = __shfl_sync(0xffffffffu, el.x, t);
            float q0 = __int_as_float(__shfl_sync(0xffffffffu, el.y, t));
            uint2 m0 = ((const uint2*)(g_msg16 + (size_t)s0 * D))[lane];
            fma_row(m0, q0, ax, ay, az, aw);
        }
    }

    float4 b = ((const float4*)bias)[lane];
    ax = fmaxf(ax + b.x, 0.f);
    ay = fmaxf(ay + b.y, 0.f);
    az = fmaxf(az + b.z, 0.f);
    aw = fmaxf(aw + b.w, 0.f);
    __half2 p0 = __floats2half2_rn(ax, ay);
    __half2 p1 = __floats2half2_rn(az, aw);
    uint2 o;
    o.x = *(unsigned int*)&p0;
    o.y = *(unsigned int*)&p1;
    ((uint2*)(g_h16 + (size_t)v * D))[lane] = o;
}

// ---------------- pool + linear ----------------
__device__ __forceinline__ int lb(const int* a, int n, int key) {
    int lo = 0, hi = n;
    while (lo < hi) {
        int m = (lo + hi) >> 1;
        if (a[m] < key) lo = m + 1; else hi = m;
    }
    return lo;
}

__global__ void k_pool(const int* __restrict__ batch,
                       const float* __restrict__ Wl,
                       const float* __restrict__ bl,
                       float* __restrict__ out, int N) {
    int g = blockIdx.x;
    __shared__ int bounds[2];
    if (threadIdx.x == 0) bounds[0] = lb(batch, N, g);
    if (threadIdx.x == 1) bounds[1] = lb(batch, N, g + 1);
    __syncthreads();
    int lo = bounds[0], hi = bounds[1];
    int t = threadIdx.x;
    float sum = 0.f;
    for (int v = lo; v < hi; v++) sum += __half2float(g_h16[(size_t)v * D + t]);
    float cnt  = (float)(hi - lo);
    float mean = sum / fmaxf(cnt, 1.f);
    float p    = mean * Wl[t];
    __shared__ float red[128];
    red[t] = p;
    __syncthreads();
    for (int off = 64; off > 0; off >>= 1) {
        if (t < off) red[t] += red[t + off];
        __syncthreads();
    }
    if (t == 0) out[g] = red[0] + bl[0];
}

// ---------------- launch ----------------
extern "C" void kernel_launch(void* const* d_in, const int* in_sizes, int n_in,
                              void* d_out, int out_size) {
    const float* x     = nullptr;
    const int*   ei    = nullptr;
    const int*   batch = nullptr;
    const float* Ws    = nullptr;
    const float* bs    = nullptr;
    const float* Wl    = nullptr;
    const float* bl    = nullptr;
    int N = 0, E = 0;

    long long sx = 0;
    for (int i = 0; i < n_in; i++) if ((long long)in_sizes[i] > sx) sx = in_sizes[i];
    N = (int)(sx / D);
    for (int i = 0; i < n_in; i++) {
        long long s = in_sizes[i];
        if (s == sx)                x     = (const float*)d_in[i];
        else if (s == (long long)N) batch = (const int*)d_in[i];
        else if (s == 4LL * D * D)  Ws    = (const float*)d_in[i];
        else if (s == 4LL * D)      bs    = (const float*)d_in[i];
        else if (s == D)            Wl    = (const float*)d_in[i];
        else if (s == 1)            bl    = (const float*)d_in[i];
        else                        { ei = (const int*)d_in[i]; E = (int)(s / 2); }
    }
    float* out = (float*)d_out;

    const int smem_bytes = 2 * 128 * AHL * 2;   // 69632 bytes
    cudaFuncSetAttribute(k_gemm_h, cudaFuncAttributeMaxDynamicSharedMemorySize, smem_bytes);

    int nb = (N + 1023) / 1024;
    int initmax = (N > 4 * D * D / 4) ? N : 4 * D * D / 4;

    k_init<<<(initmax + 255) / 256, 256>>>(Ws, N);
    k_hist<<<((E + 1) / 2 + 255) / 256, 256>>>(ei, E);
    k_scan1<<<nb, 1024>>>(N, nb);
    k_fill<<<(E + 255) / 256, 256>>>(ei, E);

    int gblocks = (N + 127) / 128;
    int aggblocks = (N * 32 + 255) / 256;
    for (int l = 0; l < 4; l++) {
        k_gemm_h<<<gblocks, 256, smem_bytes>>>(l * D * D, x, N, l == 0 ? 1 : 0);
        k_agg<<<aggblocks, 256>>>(bs + (size_t)l * D, N);
    }

    k_pool<<<out_size, 128>>>(batch, Wl, bl, out, N);
}